// round 11
// baseline (speedup 1.0000x reference)
#include <cuda_runtime.h>
#include <cuda_bf16.h>
#include <mma.h>
#include <math.h>
#include <stdint.h>

using namespace nvcuda;

#define BB 256
#define TT 256
#define FF 64
#define UU 512
#define GG 2048

#define NTILES 32
#define NCOL   64
#define KC     64
#define STAGES 3
#define NCTA   128u

#define LDA 72
#define LDB 72
#define LDZ 72
#define A_STG (64 * LDA * 2)                 // 9216 B
#define B_STG (KC * LDB * 2)                 // 9216 B
#define A_OFF 0
#define B_OFF (STAGES * A_STG)               // 27648
#define BIAS_OFF (B_OFF + STAGES * B_STG)    // 55296
#define SMEM_BYTES (BIAS_OFF + 512 + 128)

typedef __nv_bfloat16 bf16;

__device__ bf16  g_xT[TT * BB * FF];            // [t][b][f] bf16
__device__ bf16  g_img1[NTILES * 576 * NCOL];   // [tile][chunk64][k][n] packed bf16
__device__ bf16  g_img2[NTILES * 1024 * NCOL];
__device__ bf16  g_h1[2][BB * UU];
__device__ float g_c1[BB * UU];
__device__ bf16  g_h2[2][BB * UU];
__device__ float g_c2[BB * UU];
__device__ unsigned g_bar, g_gen;

__device__ __forceinline__ float sigmoidf_(float x) { return 1.f / (1.f + expf(-x)); }

#define CP_ASYNC16(dst, src) \
    asm volatile("cp.async.cg.shared.global [%0], [%1], 16;" :: "r"(dst), "l"(src))
#define CP_COMMIT() asm volatile("cp.async.commit_group;" ::: "memory")
#define CP_WAIT1()  asm volatile("cp.async.wait_group 1;" ::: "memory")

__global__ void zero_state_kernel() {
    int i = blockIdx.x * blockDim.x + threadIdx.x;
    if (i < BB * UU) {
        g_h1[0][i] = __float2bfloat16_rn(0.f);
        g_h2[0][i] = __float2bfloat16_rn(0.f);
        g_c1[i] = 0.f;
        g_c2[i] = 0.f;
    }
    if (i == 0) { g_bar = 0u; g_gen = 0u; }
}

__global__ void prep_x_kernel(const float* __restrict__ x) {
    int e = blockIdx.x * blockDim.x + threadIdx.x;   // e = b*T*F + t*F + f
    if (e >= BB * TT * FF) return;
    int f = e & 63, t = (e >> 6) & 255, b = e >> 14;
    g_xT[t * (BB * FF) + b * FF + f] = __float2bfloat16_rn(x[e]);
}

__global__ void prep_img_kernel(const float* __restrict__ Wm, const float* __restrict__ Um,
                                bf16* __restrict__ img, int KW, int Ktot) {
    int e = blockIdx.x * blockDim.x + threadIdx.x;
    if (e >= NTILES * Ktot * NCOL) return;
    int n = e & 63;
    int k = (e >> 6) % Ktot;
    int tile = e / (Ktot * NCOL);
    int g = n >> 4, ui = n & 15;
    int col = g * UU + tile * 16 + ui;
    float v = (k < KW) ? Wm[k * GG + col] : Um[(k - KW) * GG + col];
    img[tile * (Ktot * NCOL) + (k >> 6) * (KC * NCOL) + (k & 63) * NCOL + n] =
        __float2bfloat16_rn(v);
}

// release/acquire grid barrier across 128 resident CTAs (no coop launch needed)
__device__ __forceinline__ void grid_barrier(unsigned phase) {
    __threadfence();
    __syncthreads();
    if (threadIdx.x == 0) {
        unsigned old = atomicAdd(&g_bar, 1u);
        if (old == phase * NCTA - 1u) {
            atomicExch(&g_gen, phase);   // last arriver releases
        } else {
            while (*(volatile unsigned*)&g_gen < phase) __nanosleep(64);
        }
    }
    __syncthreads();
    __threadfence();
}

// One 64x64 GEMM-tile LSTM phase: z = [A0|A1][64,K] @ Wtile[K,64] + bias -> gates -> c,h
__device__ __forceinline__ void gemm_step(
    const bf16* __restrict__ src0, int ld0, int csplit,
    const bf16* __restrict__ src1,
    const bf16* __restrict__ imgb, int C,
    const float* __restrict__ bsm,
    float* __restrict__ cstate, bf16* __restrict__ hout,
    char* smem, uint32_t sb, int tid, int wid, int w_m, int w_n, int bM, int u0)
{
    bf16* As = (bf16*)smem;
    bf16* Bs = (bf16*)(smem + B_OFF);

    auto load_chunk = [&](int c, int slot) {
        const bf16* as; int lda, k0;
        if (c < csplit) { as = src0; lda = ld0; k0 = c * KC; }
        else            { as = src1; lda = UU;  k0 = (c - csplit) * KC; }
        uint32_t adst = sb + A_OFF + slot * A_STG;
#pragma unroll
        for (int j = 0; j < 4; j++) {
            int u = tid + 128 * j, m = u >> 3, kq = u & 7;
            CP_ASYNC16(adst + (uint32_t)(m * (LDA * 2) + kq * 16),
                       as + (size_t)(bM + m) * lda + k0 + kq * 8);
        }
        const char* wsrc = (const char*)imgb + (size_t)c * (KC * NCOL * 2);
        uint32_t bdst = sb + B_OFF + slot * B_STG;
#pragma unroll
        for (int j = 0; j < 4; j++) {
            int u = tid + 128 * j, k = u >> 3, nq = u & 7;
            CP_ASYNC16(bdst + (uint32_t)(k * (LDB * 2) + nq * 16), wsrc + u * 16);
        }
        CP_COMMIT();
    };

    wmma::fragment<wmma::accumulator, 16, 16, 16, float> acc[2][2];
#pragma unroll
    for (int i = 0; i < 2; i++)
#pragma unroll
        for (int j = 0; j < 2; j++) wmma::fill_fragment(acc[i][j], 0.f);

    load_chunk(0, 0);
    load_chunk(1, 1);

#pragma unroll 1
    for (int i = 0; i < C; i++) {
        CP_WAIT1();
        __syncthreads();
        int nc = i + 2;
        if (nc < C) load_chunk(nc, nc % STAGES);
        else        CP_COMMIT();

        const bf16* Ab = As + (i % STAGES) * (64 * LDA);
        const bf16* Bb = Bs + (i % STAGES) * (KC * LDB);
#pragma unroll
        for (int ks = 0; ks < 4; ks++) {
            const int kof = ks * 16;
            wmma::fragment<wmma::matrix_a, 16, 16, 16, bf16, wmma::row_major> af[2];
            wmma::fragment<wmma::matrix_b, 16, 16, 16, bf16, wmma::row_major> bfr[2];
#pragma unroll
            for (int q = 0; q < 2; q++)
                wmma::load_matrix_sync(af[q], Ab + (w_m * 32 + 16 * q) * LDA + kof, LDA);
#pragma unroll
            for (int q = 0; q < 2; q++)
                wmma::load_matrix_sync(bfr[q], Bb + kof * LDB + (w_n * 32 + 16 * q), LDB);
#pragma unroll
            for (int q = 0; q < 2; q++)
#pragma unroll
                for (int r = 0; r < 2; r++)
                    wmma::mma_sync(acc[q][r], af[q], bfr[r], acc[q][r]);
        }
    }

    __syncthreads();
    float* zs = (float*)smem;   // overlay A stages: 64*LDZ*4 = 18432 < 27648
#pragma unroll
    for (int q = 0; q < 2; q++)
#pragma unroll
        for (int r = 0; r < 2; r++)
            wmma::store_matrix_sync(zs + (w_m * 32 + 16 * q) * LDZ + (w_n * 32 + 16 * r),
                                    acc[q][r], LDZ, wmma::mem_row_major);
    __syncthreads();

    const int u  = tid & 15;
    const int b8 = tid >> 4;
    const float bi = bsm[u], bf_ = bsm[16 + u], bg = bsm[32 + u], bo = bsm[48 + u];

#pragma unroll
    for (int j = 0; j < 8; j++) {
        const int m = b8 * 8 + j;
        const size_t idx = (size_t)(bM + m) * UU + u0 + u;
        const float zi = zs[m * LDZ + u]       + bi;
        const float zf = zs[m * LDZ + 16 + u]  + bf_;
        const float zg = zs[m * LDZ + 32 + u]  + bg;
        const float zo = zs[m * LDZ + 48 + u]  + bo;
        const float ig = sigmoidf_(zi);
        const float fg = sigmoidf_(zf);
        const float gg = fmaxf(zg, 0.f);
        const float og = sigmoidf_(zo);
        const float c  = fg * cstate[idx] + ig * gg;
        cstate[idx] = c;
        hout[idx]   = __float2bfloat16_rn(og * fmaxf(c, 0.f));
    }
}

// Persistent kernel: 128 CTAs loop over all 256 steps; grid barrier between phases.
__global__ void __launch_bounds__(128, 1)
lstm_persistent(const float* __restrict__ b1, const float* __restrict__ b2)
{
    extern __shared__ __align__(1024) char smem[];
    uint32_t sb = (uint32_t)__cvta_generic_to_shared(smem);

    const int tid = threadIdx.x, wid = tid >> 5;
    const int bx = blockIdx.x;
    const int bM = (bx & 3) * 64;       // batch block
    const int tile = bx >> 2;           // unit tile
    const int u0 = tile * 16;
    const int w_m = wid & 1, w_n = wid >> 1;

    float* bsm1 = (float*)(smem + BIAS_OFF);
    float* bsm2 = bsm1 + 64;
    if (tid < 64) {
        int g = tid >> 4, ui = tid & 15;
        bsm1[tid] = b1[g * UU + tile * 16 + ui];
        bsm2[tid] = b2[g * UU + tile * 16 + ui];
    }
    __syncthreads();

    const bf16* img1b = g_img1 + (size_t)tile * (576 * NCOL);
    const bf16* img2b = g_img2 + (size_t)tile * (1024 * NCOL);

    unsigned phase = 0;
#pragma unroll 1
    for (int t = 0; t < TT; t++) {
        gemm_step(g_xT + (size_t)t * BB * FF, FF, 1, g_h1[t & 1],
                  img1b, 9, bsm1, g_c1, g_h1[(t + 1) & 1],
                  smem, sb, tid, wid, w_m, w_n, bM, u0);
        grid_barrier(++phase);
        gemm_step(g_h1[(t + 1) & 1], UU, 8, g_h2[t & 1],
                  img2b, 16, bsm2, g_c2, g_h2[(t + 1) & 1],
                  smem, sb, tid, wid, w_m, w_n, bM, u0);
        grid_barrier(++phase);
    }
}

__global__ void head_kernel(const float* __restrict__ Wd,
                            const float* __restrict__ bd,
                            float* __restrict__ out)
{
    const int b = threadIdx.x;
    float s = 0.f;
#pragma unroll 8
    for (int k = 0; k < UU; k++) s = fmaf(__bfloat162float(g_h2[0][b * UU + k]), Wd[k], s);
    out[b] = 1.f / (1.f + expf(-(s + bd[0])));
}

extern "C" void kernel_launch(void* const* d_in, const int* in_sizes, int n_in,
                              void* d_out, int out_size) {
    const float* x  = (const float*)d_in[0];
    const float* W1 = (const float*)d_in[1];
    const float* U1 = (const float*)d_in[2];
    const float* b1 = (const float*)d_in[3];
    const float* W2 = (const float*)d_in[4];
    const float* U2 = (const float*)d_in[5];
    const float* b2 = (const float*)d_in[6];
    const float* Wd = (const float*)d_in[7];
    const float* bd = (const float*)d_in[8];
    float* out = (float*)d_out;

    cudaFuncSetAttribute(lstm_persistent, cudaFuncAttributeMaxDynamicSharedMemorySize, SMEM_BYTES);

    bf16 *img1, *img2;
    cudaGetSymbolAddress((void**)&img1, g_img1);
    cudaGetSymbolAddress((void**)&img2, g_img2);

    zero_state_kernel<<<(BB * UU + 255) / 256, 256>>>();
    prep_x_kernel<<<(BB * TT * FF + 255) / 256, 256>>>(x);
    prep_img_kernel<<<(NTILES * 576 * NCOL + 255) / 256, 256>>>(W1, U1, img1, FF, 576);
    prep_img_kernel<<<(NTILES * 1024 * NCOL + 255) / 256, 256>>>(W2, U2, img2, UU, 1024);

    lstm_persistent<<<NCTA, 128, SMEM_BYTES>>>(b1, b2);

    head_kernel<<<1, 256>>>(Wd, bd, out);
}

// round 12
// speedup vs baseline: 1.0675x; 1.0675x over previous
#include <cuda_runtime.h>
#include <cuda_bf16.h>
#include <mma.h>
#include <math.h>
#include <stdint.h>

using namespace nvcuda;

#define BB 256
#define TT 256
#define FF 64
#define UU 512
#define GG 2048

#define NTILES 32      // 32 unit-tiles of 16 units; CTA N = 4 gates x 16 units = 64
#define NCOL   64
#define KC     64      // K per chunk (4 k16-slices)
#define STAGES 3
#define NTHR   256     // 8 warps: 4 (m) x 2 (n), warp tile 16x32

#define LDA 72         // A smem stride (halfs)
#define LDB 72         // B smem stride (halfs)
#define LDZ 72         // z smem stride (floats)
#define A_STG (64 * LDA * 2)                 // 9216 B
#define B_STG (KC * LDB * 2)                 // 9216 B
#define A_OFF 0
#define B_OFF (STAGES * A_STG)               // 27648
#define BIAS_OFF (B_OFF + STAGES * B_STG)    // 55296
#define SMEM_BYTES (BIAS_OFF + 256 + 128)

typedef __nv_bfloat16 bf16;

__device__ bf16  g_xT[TT * BB * FF];            // [t][b][f] bf16
__device__ bf16  g_img1[NTILES * 576 * NCOL];   // [tile][chunk64][k][n] packed bf16
__device__ bf16  g_img2[NTILES * 1024 * NCOL];
__device__ bf16  g_h1[2][BB * UU];
__device__ float g_c1[BB * UU];
__device__ bf16  g_h2[2][BB * UU];
__device__ float g_c2[BB * UU];

__device__ __forceinline__ float sigmoidf_(float x) { return 1.f / (1.f + expf(-x)); }

#define CP_ASYNC16(dst, src) \
    asm volatile("cp.async.cg.shared.global [%0], [%1], 16;" :: "r"(dst), "l"(src))
#define CP_COMMIT() asm volatile("cp.async.commit_group;" ::: "memory")
#define CP_WAIT1()  asm volatile("cp.async.wait_group 1;" ::: "memory")

__global__ void zero_state_kernel() {
    int i = blockIdx.x * blockDim.x + threadIdx.x;
    if (i < BB * UU) {
        g_h1[0][i] = __float2bfloat16_rn(0.f);
        g_h2[0][i] = __float2bfloat16_rn(0.f);
        g_c1[i] = 0.f;
        g_c2[i] = 0.f;
    }
}

__global__ void prep_x_kernel(const float* __restrict__ x) {
    int e = blockIdx.x * blockDim.x + threadIdx.x;   // e = b*T*F + t*F + f
    if (e >= BB * TT * FF) return;
    int f = e & 63, t = (e >> 6) & 255, b = e >> 14;
    g_xT[t * (BB * FF) + b * FF + f] = __float2bfloat16_rn(x[e]);
}

// Weight image: per unit-tile, per 64-K chunk, packed [k][n] (n=g*16+ui -> col g*512+tile*16+ui).
__global__ void prep_img_kernel(const float* __restrict__ Wm, const float* __restrict__ Um,
                                bf16* __restrict__ img, int KW, int Ktot) {
    int e = blockIdx.x * blockDim.x + threadIdx.x;
    if (e >= NTILES * Ktot * NCOL) return;
    int n = e & 63;
    int k = (e >> 6) % Ktot;
    int tile = e / (Ktot * NCOL);
    int g = n >> 4, ui = n & 15;
    int col = g * UU + tile * 16 + ui;
    float v = (k < KW) ? Wm[k * GG + col] : Um[(k - KW) * GG + col];
    img[tile * (Ktot * NCOL) + (k >> 6) * (KC * NCOL) + (k & 63) * NCOL + n] =
        __float2bfloat16_rn(v);
}

// grid (4, 32), block 256 (8 warps, 4x2, warp tile 16x32):
// z[64b x 64n] = [A0|A1][64,K] @ Wtile[K,64] via wmma bf16 m16n16k16,
// register ks-pipelined fragments; 3-stage cp.async; 1 sync/chunk.
__global__ void __launch_bounds__(NTHR, 1)
lstm_step_mma(const bf16* __restrict__ src0, int ld0, int csplit,
              const bf16* __restrict__ src1,
              const bf16* __restrict__ img, int imgTileHalfs, int C,
              const float* __restrict__ bias,
              float* __restrict__ cstate,
              bf16* __restrict__ hout)
{
    extern __shared__ __align__(1024) char smem[];
    uint32_t sb = (uint32_t)__cvta_generic_to_shared(smem);
    bf16* As = (bf16*)smem;                  // per stage: [64][LDA]
    bf16* Bs = (bf16*)(smem + B_OFF);        // per stage: [KC][LDB]
    float* bsm = (float*)(smem + BIAS_OFF);

    const int tid = threadIdx.x, wid = tid >> 5;
    const int bM = blockIdx.x * 64, tile = blockIdx.y;
    const int w_m = wid & 3;        // 4 m-tiles of 16 rows
    const int w_n = wid >> 2;       // 2 n-tiles of 32 cols

    if (tid < 64) {
        int g = tid >> 4, ui = tid & 15;
        bsm[tid] = bias[g * UU + tile * 16 + ui];
    }

    const char* imgb = (const char*)(img + (size_t)tile * imgTileHalfs);

    auto load_chunk = [&](int c, int slot) {
        // A: 64 rows x 64 halfs (128B/row = 8 x 16B) -> [m][LDA]; 512 units over 256 thr
        const bf16* as; int lda, k0;
        if (c < csplit) { as = src0; lda = ld0; k0 = c * KC; }
        else            { as = src1; lda = UU;  k0 = (c - csplit) * KC; }
        uint32_t adst = sb + A_OFF + slot * A_STG;
#pragma unroll
        for (int j = 0; j < 2; j++) {
            int u = tid + NTHR * j, m = u >> 3, kq = u & 7;
            CP_ASYNC16(adst + (uint32_t)(m * (LDA * 2) + kq * 16),
                       as + (size_t)(bM + m) * lda + k0 + kq * 8);
        }
        // B: verbatim packed [k 64][n 64] bf16
        const char* wsrc = imgb + (size_t)c * (KC * NCOL * 2);
        uint32_t bdst = sb + B_OFF + slot * B_STG;
#pragma unroll
        for (int j = 0; j < 2; j++) {
            int u = tid + NTHR * j, k = u >> 3, nq = u & 7;
            CP_ASYNC16(bdst + (uint32_t)(k * (LDB * 2) + nq * 16), wsrc + u * 16);
        }
        CP_COMMIT();
    };

    wmma::fragment<wmma::accumulator, 16, 16, 16, float> acc[2];
#pragma unroll
    for (int r = 0; r < 2; r++) wmma::fill_fragment(acc[r], 0.f);

    load_chunk(0, 0);
    load_chunk(1, 1);

#pragma unroll 1
    for (int i = 0; i < C; i++) {
        CP_WAIT1();          // chunk i's group complete (<=1 outstanding: chunk i+1)
        __syncthreads();     // CTA-wide ready; slot (i-1)%3 fully consumed
        int nc = i + 2;
        if (nc < C) load_chunk(nc, nc % STAGES);
        else        CP_COMMIT();

        const bf16* Ab = As + (i % STAGES) * (64 * LDA) + (w_m * 16) * LDA;
        const bf16* Bb = Bs + (i % STAGES) * (KC * LDB) + w_n * 32;

        wmma::fragment<wmma::matrix_a, 16, 16, 16, bf16, wmma::row_major> af[2];
        wmma::fragment<wmma::matrix_b, 16, 16, 16, bf16, wmma::row_major> bfr[2][2];
        wmma::load_matrix_sync(af[0], Ab, LDA);
        wmma::load_matrix_sync(bfr[0][0], Bb, LDB);
        wmma::load_matrix_sync(bfr[0][1], Bb + 16, LDB);
#pragma unroll
        for (int ks = 0; ks < 4; ks++) {
            const int cur = ks & 1, nxt = cur ^ 1;
            if (ks < 3) {
                const int kof = (ks + 1) * 16;
                wmma::load_matrix_sync(af[nxt], Ab + kof, LDA);
                wmma::load_matrix_sync(bfr[nxt][0], Bb + kof * LDB, LDB);
                wmma::load_matrix_sync(bfr[nxt][1], Bb + kof * LDB + 16, LDB);
            }
            wmma::mma_sync(acc[0], af[cur], bfr[cur][0], acc[0]);
            wmma::mma_sync(acc[1], af[cur], bfr[cur][1], acc[1]);
        }
    }

    // ---- epilogue: stage z[64][64] f32 in smem (overlay A stages), then gate math ----
    __syncthreads();
    float* zs = (float*)smem;   // 64*LDZ*4 = 18432 B < A region (27648 B)
#pragma unroll
    for (int r = 0; r < 2; r++)
        wmma::store_matrix_sync(zs + (w_m * 16) * LDZ + (w_n * 32 + 16 * r),
                                acc[r], LDZ, wmma::mem_row_major);
    __syncthreads();

    const int u  = tid & 15;        // unit within tile
    const int bq = tid >> 4;        // batch quad (4 rows each)
    const int u0 = tile * 16;
    const float bi = bsm[u], bf_ = bsm[16 + u], bg = bsm[32 + u], bo = bsm[48 + u];

#pragma unroll
    for (int j = 0; j < 4; j++) {
        const int m = bq * 4 + j;               // local batch row 0..63
        const size_t idx = (size_t)(bM + m) * UU + u0 + u;
        const float zi = zs[m * LDZ + u]       + bi;
        const float zf = zs[m * LDZ + 16 + u]  + bf_;
        const float zg = zs[m * LDZ + 32 + u]  + bg;
        const float zo = zs[m * LDZ + 48 + u]  + bo;
        const float ig = sigmoidf_(zi);
        const float fg = sigmoidf_(zf);
        const float gg = fmaxf(zg, 0.f);
        const float og = sigmoidf_(zo);
        const float c  = fg * cstate[idx] + ig * gg;
        cstate[idx] = c;
        hout[idx]   = __float2bfloat16_rn(og * fmaxf(c, 0.f));
    }
}

__global__ void head_kernel(const bf16* __restrict__ h2,
                            const float* __restrict__ Wd,
                            const float* __restrict__ bd,
                            float* __restrict__ out)
{
    const int b = threadIdx.x;
    float s = 0.f;
#pragma unroll 8
    for (int k = 0; k < UU; k++) s = fmaf(__bfloat162float(h2[b * UU + k]), Wd[k], s);
    out[b] = 1.f / (1.f + expf(-(s + bd[0])));
}

extern "C" void kernel_launch(void* const* d_in, const int* in_sizes, int n_in,
                              void* d_out, int out_size) {
    const float* x  = (const float*)d_in[0];
    const float* W1 = (const float*)d_in[1];
    const float* U1 = (const float*)d_in[2];
    const float* b1 = (const float*)d_in[3];
    const float* W2 = (const float*)d_in[4];
    const float* U2 = (const float*)d_in[5];
    const float* b2 = (const float*)d_in[6];
    const float* Wd = (const float*)d_in[7];
    const float* bd = (const float*)d_in[8];
    float* out = (float*)d_out;

    cudaFuncSetAttribute(lstm_step_mma, cudaFuncAttributeMaxDynamicSharedMemorySize, SMEM_BYTES);

    bf16 *xT, *img1, *img2, *h1b, *h2b;
    float *c1, *c2;
    cudaGetSymbolAddress((void**)&xT,   g_xT);
    cudaGetSymbolAddress((void**)&img1, g_img1);
    cudaGetSymbolAddress((void**)&img2, g_img2);
    cudaGetSymbolAddress((void**)&h1b,  g_h1);
    cudaGetSymbolAddress((void**)&c1,   g_c1);
    cudaGetSymbolAddress((void**)&h2b,  g_h2);
    cudaGetSymbolAddress((void**)&c2,   g_c2);
    bf16* h1[2] = { h1b, h1b + BB * UU };
    bf16* h2[2] = { h2b, h2b + BB * UU };

    zero_state_kernel<<<(BB * UU + 255) / 256, 256>>>();
    prep_x_kernel<<<(BB * TT * FF + 255) / 256, 256>>>(x);
    prep_img_kernel<<<(NTILES * 576 * NCOL + 255) / 256, 256>>>(W1, U1, img1, FF, 576);
    prep_img_kernel<<<(NTILES * 1024 * NCOL + 255) / 256, 256>>>(W2, U2, img2, UU, 1024);

    dim3 grid(BB / 64, NTILES);  // 4 x 32 = 128 CTAs
    for (int t = 0; t < TT; t++) {
        lstm_step_mma<<<grid, NTHR, SMEM_BYTES>>>(
            xT + t * BB * FF, FF, 1, h1[t & 1],
            img1, 576 * NCOL, 9, b1, c1, h1[(t + 1) & 1]);
        lstm_step_mma<<<grid, NTHR, SMEM_BYTES>>>(
            h1[(t + 1) & 1], UU, 8, h2[t & 1],
            img2, 1024 * NCOL, 16, b2, c2, h2[(t + 1) & 1]);
    }
    head_kernel<<<1, 256>>>(h2[0], Wd, bd, out);
}

// round 13
// speedup vs baseline: 1.1750x; 1.1007x over previous
#include <cuda_runtime.h>
#include <cuda_bf16.h>
#include <mma.h>
#include <math.h>
#include <stdint.h>

using namespace nvcuda;

#define BB 256
#define TT 256
#define FF 64
#define UU 512
#define GG 2048

#define NTILES 32      // 32 unit-tiles of 16 units; CTA N = 4 gates x 16 units = 64
#define NCOL   64
#define KC     64      // K per chunk (4 k16-slices; 2 per k-half)
#define STAGES 3
#define NTHR   256     // 8 warps: 2m x 2n x 2k, warp tile 32x32

#define LDA 72         // A smem stride (halfs)
#define LDB 72         // B smem stride (halfs)
#define LDZ 72         // z smem stride (floats)
#define A_STG (64 * LDA * 2)                 // 9216 B
#define B_STG (KC * LDB * 2)                 // 9216 B
#define A_OFF 0
#define B_OFF (STAGES * A_STG)               // 27648
#define Z_STG (64 * LDZ * 4)                 // 18432 B (two z buffers overlay A+B stages)
#define BIAS_OFF (B_OFF + STAGES * B_STG)    // 55296
#define SMEM_BYTES (BIAS_OFF + 256 + 128)

typedef __nv_bfloat16 bf16;

__device__ bf16  g_xT[TT * BB * FF];            // [t][b][f] bf16
__device__ bf16  g_img1[NTILES * 576 * NCOL];   // [tile][chunk64][k][n] packed bf16
__device__ bf16  g_img2[NTILES * 1024 * NCOL];
__device__ bf16  g_h1[2][BB * UU];
__device__ float g_c1[BB * UU];
__device__ bf16  g_h2[2][BB * UU];
__device__ float g_c2[BB * UU];

__device__ __forceinline__ float sigmoidf_(float x) { return 1.f / (1.f + expf(-x)); }

#define CP_ASYNC16(dst, src) \
    asm volatile("cp.async.cg.shared.global [%0], [%1], 16;" :: "r"(dst), "l"(src))
#define CP_COMMIT() asm volatile("cp.async.commit_group;" ::: "memory")
#define CP_WAIT1()  asm volatile("cp.async.wait_group 1;" ::: "memory")

// ---- single consolidated prep kernel (keeps ncu -s 5 on the hot kernel) ----
#define NB_ZERO 512
#define NB_X    16384
#define NB_I1   4608    // NTILES*576*NCOL / 256
#define NB_I2   8192    // NTILES*1024*NCOL / 256

__device__ __forceinline__ void img_elem(const float* Wm, const float* Um,
                                         bf16* img, int KW, int Ktot, int e) {
    int n = e & 63;
    int k = (e >> 6) % Ktot;
    int tile = e / (Ktot * NCOL);
    int g = n >> 4, ui = n & 15;
    int col = g * UU + tile * 16 + ui;
    float v = (k < KW) ? Wm[k * GG + col] : Um[(k - KW) * GG + col];
    img[tile * (Ktot * NCOL) + (k >> 6) * (KC * NCOL) + (k & 63) * NCOL + n] =
        __float2bfloat16_rn(v);
}

__global__ void prep_all_kernel(const float* __restrict__ x,
                                const float* __restrict__ W1, const float* __restrict__ U1,
                                const float* __restrict__ W2, const float* __restrict__ U2) {
    int bx = blockIdx.x;
    if (bx < NB_ZERO) {
        int i = bx * 256 + threadIdx.x;
        g_h1[0][i] = __float2bfloat16_rn(0.f);
        g_h2[0][i] = __float2bfloat16_rn(0.f);
        g_c1[i] = 0.f;
        g_c2[i] = 0.f;
    } else if (bx < NB_ZERO + NB_X) {
        int e = (bx - NB_ZERO) * 256 + threadIdx.x;   // e = b*T*F + t*F + f
        int f = e & 63, t = (e >> 6) & 255, b = e >> 14;
        g_xT[t * (BB * FF) + b * FF + f] = __float2bfloat16_rn(x[e]);
    } else if (bx < NB_ZERO + NB_X + NB_I1) {
        int e = (bx - NB_ZERO - NB_X) * 256 + threadIdx.x;
        img_elem(W1, U1, g_img1, FF, 576, e);
    } else {
        int e = (bx - NB_ZERO - NB_X - NB_I1) * 256 + threadIdx.x;
        img_elem(W2, U2, g_img2, UU, 1024, e);
    }
}

// grid (4, 32), block 256 (8 warps: 2m x 2n x 2k, warp tile 32x32):
// z[64b x 64n] = [A0|A1][64,K] @ Wtile[K,64] via wmma bf16 m16n16k16.
// K-split: w_k halves each chunk's 4 k16-slices; partials summed in smem epilogue.
__global__ void __launch_bounds__(NTHR, 1)
lstm_step_mma(const bf16* __restrict__ src0, int ld0, int csplit,
              const bf16* __restrict__ src1,
              const bf16* __restrict__ img, int imgTileHalfs, int C,
              const float* __restrict__ bias,
              float* __restrict__ cstate,
              bf16* __restrict__ hout)
{
    extern __shared__ __align__(1024) char smem[];
    uint32_t sb = (uint32_t)__cvta_generic_to_shared(smem);
    bf16* As = (bf16*)smem;                  // per stage: [64][LDA]
    bf16* Bs = (bf16*)(smem + B_OFF);        // per stage: [KC][LDB]
    float* bsm = (float*)(smem + BIAS_OFF);

    const int tid = threadIdx.x, wid = tid >> 5;
    const int bM = blockIdx.x * 64, tile = blockIdx.y;
    const int w_m = wid & 1;          // 2 m-tiles of 32 rows
    const int w_n = (wid >> 1) & 1;   // 2 n-tiles of 32 cols
    const int w_k = wid >> 2;         // 2 k-halves (2 k16-slices each)

    if (tid < 64) {
        int g = tid >> 4, ui = tid & 15;
        bsm[tid] = bias[g * UU + tile * 16 + ui];
    }

    const char* imgb = (const char*)(img + (size_t)tile * imgTileHalfs);

    auto load_chunk = [&](int c, int slot) {
        const bf16* as; int lda, k0;
        if (c < csplit) { as = src0; lda = ld0; k0 = c * KC; }
        else            { as = src1; lda = UU;  k0 = (c - csplit) * KC; }
        uint32_t adst = sb + A_OFF + slot * A_STG;
#pragma unroll
        for (int j = 0; j < 2; j++) {
            int u = tid + NTHR * j, m = u >> 3, kq = u & 7;
            CP_ASYNC16(adst + (uint32_t)(m * (LDA * 2) + kq * 16),
                       as + (size_t)(bM + m) * lda + k0 + kq * 8);
        }
        const char* wsrc = imgb + (size_t)c * (KC * NCOL * 2);
        uint32_t bdst = sb + B_OFF + slot * B_STG;
#pragma unroll
        for (int j = 0; j < 2; j++) {
            int u = tid + NTHR * j, k = u >> 3, nq = u & 7;
            CP_ASYNC16(bdst + (uint32_t)(k * (LDB * 2) + nq * 16), wsrc + u * 16);
        }
        CP_COMMIT();
    };

    wmma::fragment<wmma::accumulator, 16, 16, 16, float> acc[2][2];
#pragma unroll
    for (int q = 0; q < 2; q++)
#pragma unroll
        for (int r = 0; r < 2; r++) wmma::fill_fragment(acc[q][r], 0.f);

    load_chunk(0, 0);
    load_chunk(1, 1);

#pragma unroll 1
    for (int i = 0; i < C; i++) {
        CP_WAIT1();          // chunk i's group complete (<=1 outstanding)
        __syncthreads();     // CTA-wide ready; slot (i-1)%3 fully consumed
        int nc = i + 2;
        if (nc < C) load_chunk(nc, nc % STAGES);
        else        CP_COMMIT();

        const bf16* Ab = As + (i % STAGES) * (64 * LDA) + (w_m * 32) * LDA;
        const bf16* Bb = Bs + (i % STAGES) * (KC * LDB) + w_n * 32;
        const int kof0 = (w_k * 2) * 16;     // this warp's 2 k16-slices

        wmma::fragment<wmma::matrix_a, 16, 16, 16, bf16, wmma::row_major> af[2][2];
        wmma::fragment<wmma::matrix_b, 16, 16, 16, bf16, wmma::row_major> bfr[2][2];
        wmma::load_matrix_sync(af[0][0], Ab + kof0, LDA);
        wmma::load_matrix_sync(af[0][1], Ab + 16 * LDA + kof0, LDA);
        wmma::load_matrix_sync(bfr[0][0], Bb + kof0 * LDB, LDB);
        wmma::load_matrix_sync(bfr[0][1], Bb + kof0 * LDB + 16, LDB);
#pragma unroll
        for (int s = 0; s < 2; s++) {
            if (s == 0) {   // prefetch second slice while first computes
                const int kof1 = kof0 + 16;
                wmma::load_matrix_sync(af[1][0], Ab + kof1, LDA);
                wmma::load_matrix_sync(af[1][1], Ab + 16 * LDA + kof1, LDA);
                wmma::load_matrix_sync(bfr[1][0], Bb + kof1 * LDB, LDB);
                wmma::load_matrix_sync(bfr[1][1], Bb + kof1 * LDB + 16, LDB);
            }
#pragma unroll
            for (int q = 0; q < 2; q++)
#pragma unroll
                for (int r = 0; r < 2; r++)
                    wmma::mma_sync(acc[q][r], af[s][q], bfr[s][r], acc[q][r]);
        }
    }

    // ---- epilogue: two z buffers (one per k-half), summed during gate math ----
    __syncthreads();
    float* zs0 = (float*)smem;                    // [64][LDZ]
    float* zs1 = (float*)(smem + Z_STG);          // [64][LDZ] (fits in A+B region)
    float* zsw = w_k ? zs1 : zs0;
#pragma unroll
    for (int q = 0; q < 2; q++)
#pragma unroll
        for (int r = 0; r < 2; r++)
            wmma::store_matrix_sync(zsw + (w_m * 32 + 16 * q) * LDZ + (w_n * 32 + 16 * r),
                                    acc[q][r], LDZ, wmma::mem_row_major);
    __syncthreads();

    const int u  = tid & 15;
    const int bq = tid >> 4;
    const int u0 = tile * 16;
    const float bi = bsm[u], bf_ = bsm[16 + u], bg = bsm[32 + u], bo = bsm[48 + u];

#pragma unroll
    for (int j = 0; j < 4; j++) {
        const int m = bq * 4 + j;
        const size_t idx = (size_t)(bM + m) * UU + u0 + u;
        const float zi = zs0[m * LDZ + u]      + zs1[m * LDZ + u]      + bi;
        const float zf = zs0[m * LDZ + 16 + u] + zs1[m * LDZ + 16 + u] + bf_;
        const float zg = zs0[m * LDZ + 32 + u] + zs1[m * LDZ + 32 + u] + bg;
        const float zo = zs0[m * LDZ + 48 + u] + zs1[m * LDZ + 48 + u] + bo;
        const float ig = sigmoidf_(zi);
        const float fg = sigmoidf_(zf);
        const float gg = fmaxf(zg, 0.f);
        const float og = sigmoidf_(zo);
        const float c  = fg * cstate[idx] + ig * gg;
        cstate[idx] = c;
        hout[idx]   = __float2bfloat16_rn(og * fmaxf(c, 0.f));
    }
}

__global__ void head_kernel(const float* __restrict__ Wd,
                            const float* __restrict__ bd,
                            float* __restrict__ out)
{
    const int b = threadIdx.x;
    float s = 0.f;
#pragma unroll 8
    for (int k = 0; k < UU; k++) s = fmaf(__bfloat162float(g_h2[0][b * UU + k]), Wd[k], s);
    out[b] = 1.f / (1.f + expf(-(s + bd[0])));
}

extern "C" void kernel_launch(void* const* d_in, const int* in_sizes, int n_in,
                              void* d_out, int out_size) {
    const float* x  = (const float*)d_in[0];
    const float* W1 = (const float*)d_in[1];
    const float* U1 = (const float*)d_in[2];
    const float* b1 = (const float*)d_in[3];
    const float* W2 = (const float*)d_in[4];
    const float* U2 = (const float*)d_in[5];
    const float* b2 = (const float*)d_in[6];
    const float* Wd = (const float*)d_in[7];
    const float* bd = (const float*)d_in[8];
    float* out = (float*)d_out;

    cudaFuncSetAttribute(lstm_step_mma, cudaFuncAttributeMaxDynamicSharedMemorySize, SMEM_BYTES);

    bf16 *xT, *img1, *img2, *h1b, *h2b;
    float *c1, *c2;
    cudaGetSymbolAddress((void**)&xT,   g_xT);
    cudaGetSymbolAddress((void**)&img1, g_img1);
    cudaGetSymbolAddress((void**)&img2, g_img2);
    cudaGetSymbolAddress((void**)&h1b,  g_h1);
    cudaGetSymbolAddress((void**)&c1,   g_c1);
    cudaGetSymbolAddress((void**)&h2b,  g_h2);
    cudaGetSymbolAddress((void**)&c2,   g_c2);
    bf16* h1[2] = { h1b, h1b + BB * UU };
    bf16* h2[2] = { h2b, h2b + BB * UU };

    prep_all_kernel<<<NB_ZERO + NB_X + NB_I1 + NB_I2, 256>>>(x, W1, U1, W2, U2);

    dim3 grid(BB / 64, NTILES);  // 4 x 32 = 128 CTAs
    for (int t = 0; t < TT; t++) {
        lstm_step_mma<<<grid, NTHR, SMEM_BYTES>>>(
            xT + t * BB * FF, FF, 1, h1[t & 1],
            img1, 576 * NCOL, 9, b1, c1, h1[(t + 1) & 1]);
        lstm_step_mma<<<grid, NTHR, SMEM_BYTES>>>(
            h1[(t + 1) & 1], UU, 8, h2[t & 1],
            img2, 1024 * NCOL, 16, b2, c2, h2[(t + 1) & 1]);
    }
    head_kernel<<<1, 256>>>(Wd, bd, out);
}

// round 15
// speedup vs baseline: 1.1972x; 1.0189x over previous
#include <cuda_runtime.h>
#include <cuda_bf16.h>
#include <mma.h>
#include <math.h>
#include <stdint.h>

using namespace nvcuda;

#define BB 256
#define TT 256
#define FF 64
#define UU 512
#define GG 2048

#define NTILES 32
#define NCOL   64
#define KC     64
#define STAGES 3
#define NTHR   256
#define NCTA   128u

#define LDA 72
#define LDB 72
#define LDZ 72
#define A_STG   (64 * LDA * 2)               // 9216
#define B_STG   (KC * LDB * 2)               // 9216
#define A_OFF   0
#define B1_OFF  (STAGES * A_STG)             // 27648
#define WB2_OFF (B1_OFF + STAGES * B_STG)    // 55296
#define WB2_SZ  (1024 * LDB * 2)             // 147456
#define BIAS_OFF (WB2_OFF + WB2_SZ)          // 202752
#define SMEM_BYTES (BIAS_OFF + 512 + 128)
#define Z1_OFF  (64 * LDZ * 4)               // zs1 at 18432 (z overlays A+B1 stage region)

typedef __nv_bfloat16 bf16;

__device__ bf16  g_xT[TT * BB * FF];
__device__ bf16  g_img1[NTILES * 576 * NCOL];
__device__ bf16  g_img2[NTILES * 1024 * NCOL];
__device__ bf16  g_h1[2][BB * UU];
__device__ float g_c1[BB * UU];
__device__ bf16  g_h2[2][BB * UU];
__device__ float g_c2[BB * UU];
__device__ unsigned g_bar, g_gen;

__device__ __forceinline__ float sigmoidf_(float x) { return 1.f / (1.f + expf(-x)); }

#define CP_ASYNC16(dst, src) \
    asm volatile("cp.async.cg.shared.global [%0], [%1], 16;" :: "r"(dst), "l"(src))
#define CP_COMMIT() asm volatile("cp.async.commit_group;" ::: "memory")
#define CP_WAIT1()  asm volatile("cp.async.wait_group 1;" ::: "memory")
#define CP_WAIT0()  asm volatile("cp.async.wait_group 0;" ::: "memory")

// ---- consolidated prep ----
#define NB_ZERO 512
#define NB_X    16384
#define NB_I1   4608
#define NB_I2   8192

__device__ __forceinline__ void img_elem(const float* Wm, const float* Um,
                                         bf16* img, int KW, int Ktot, int e) {
    int n = e & 63;
    int k = (e >> 6) % Ktot;
    int tile = e / (Ktot * NCOL);
    int g = n >> 4, ui = n & 15;
    int col = g * UU + tile * 16 + ui;
    float v = (k < KW) ? Wm[k * GG + col] : Um[(k - KW) * GG + col];
    img[tile * (Ktot * NCOL) + (k >> 6) * (KC * NCOL) + (k & 63) * NCOL + n] =
        __float2bfloat16_rn(v);
}

__global__ void prep_all_kernel(const float* __restrict__ x,
                                const float* __restrict__ W1, const float* __restrict__ U1,
                                const float* __restrict__ W2, const float* __restrict__ U2) {
    int bx = blockIdx.x;
    if (bx < NB_ZERO) {
        int i = bx * 256 + threadIdx.x;
        g_h1[0][i] = __float2bfloat16_rn(0.f);
        g_h2[0][i] = __float2bfloat16_rn(0.f);
        g_c1[i] = 0.f;
        g_c2[i] = 0.f;
        if (i == 0) { g_bar = 0u; g_gen = 0u; }
    } else if (bx < NB_ZERO + NB_X) {
        int e = (bx - NB_ZERO) * 256 + threadIdx.x;
        int f = e & 63, t = (e >> 6) & 255, b = e >> 14;
        g_xT[t * (BB * FF) + b * FF + f] = __float2bfloat16_rn(x[e]);
    } else if (bx < NB_ZERO + NB_X + NB_I1) {
        int e = (bx - NB_ZERO - NB_X) * 256 + threadIdx.x;
        img_elem(W1, U1, g_img1, FF, 576, e);
    } else {
        int e = (bx - NB_ZERO - NB_X - NB_I1) * 256 + threadIdx.x;
        img_elem(W2, U2, g_img2, UU, 1024, e);
    }
}

// release/acquire grid barrier across 128 resident CTAs
__device__ __forceinline__ void grid_barrier(unsigned phase) {
    __threadfence();
    __syncthreads();
    if (threadIdx.x == 0) {
        unsigned old = atomicAdd(&g_bar, 1u);
        if (old == phase * NCTA - 1u) {
            atomicExch(&g_gen, phase);
        } else {
            while (*(volatile unsigned*)&g_gen < phase) __nanosleep(64);
        }
    }
    __syncthreads();
    __threadfence();
}

// One 64x64 phase. RESB: B from resident smem (layer2) vs streamed ring (layer1).
template <bool RESB>
__device__ __forceinline__ void gemm_phase(
    const bf16* __restrict__ src0, int ld0, int csplit,
    const bf16* __restrict__ src1,
    const bf16* __restrict__ imgb, int C,
    const float* __restrict__ bsm,
    float* __restrict__ cstate, bf16* __restrict__ hout,
    char* smem, uint32_t sb, int tid, int w_m, int w_n, int w_k, int bM, int u0)
{
    bf16* As = (bf16*)smem;

    auto load_chunk = [&](int c, int slot) {
        const bf16* as; int lda, k0;
        if (c < csplit) { as = src0; lda = ld0; k0 = c * KC; }
        else            { as = src1; lda = UU;  k0 = (c - csplit) * KC; }
        uint32_t adst = sb + A_OFF + slot * A_STG;
#pragma unroll
        for (int j = 0; j < 2; j++) {
            int u = tid + NTHR * j, m = u >> 3, kq = u & 7;
            CP_ASYNC16(adst + (uint32_t)(m * (LDA * 2) + kq * 16),
                       as + (size_t)(bM + m) * lda + k0 + kq * 8);
        }
        if (!RESB) {
            const char* wsrc = (const char*)imgb + (size_t)c * (KC * NCOL * 2);
            uint32_t bdst = sb + B1_OFF + slot * B_STG;
#pragma unroll
            for (int j = 0; j < 2; j++) {
                int u = tid + NTHR * j, k = u >> 3, nq = u & 7;
                CP_ASYNC16(bdst + (uint32_t)(k * (LDB * 2) + nq * 16), wsrc + u * 16);
            }
        }
        CP_COMMIT();
    };

    wmma::fragment<wmma::accumulator, 16, 16, 16, float> acc[2][2];
#pragma unroll
    for (int q = 0; q < 2; q++)
#pragma unroll
        for (int r = 0; r < 2; r++) wmma::fill_fragment(acc[q][r], 0.f);

    load_chunk(0, 0);
    load_chunk(1, 1);

#pragma unroll 1
    for (int i = 0; i < C; i++) {
        CP_WAIT1();
        __syncthreads();
        int nc = i + 2;
        if (nc < C) load_chunk(nc, nc % STAGES);
        else        CP_COMMIT();

        const bf16* Ab = As + (i % STAGES) * (64 * LDA) + (w_m * 32) * LDA;
        const bf16* Bb = RESB
            ? (const bf16*)(smem + WB2_OFF) + (size_t)i * KC * LDB + w_n * 32
            : (const bf16*)(smem + B1_OFF) + (i % STAGES) * (KC * LDB) + w_n * 32;
        const int kof0 = (w_k * 2) * 16;

        wmma::fragment<wmma::matrix_a, 16, 16, 16, bf16, wmma::row_major> af[2][2];
        wmma::fragment<wmma::matrix_b, 16, 16, 16, bf16, wmma::row_major> bfr[2][2];
        wmma::load_matrix_sync(af[0][0], Ab + kof0, LDA);
        wmma::load_matrix_sync(af[0][1], Ab + 16 * LDA + kof0, LDA);
        wmma::load_matrix_sync(bfr[0][0], Bb + kof0 * LDB, LDB);
        wmma::load_matrix_sync(bfr[0][1], Bb + kof0 * LDB + 16, LDB);
#pragma unroll
        for (int s = 0; s < 2; s++) {
            if (s == 0) {
                const int kof1 = kof0 + 16;
                wmma::load_matrix_sync(af[1][0], Ab + kof1, LDA);
                wmma::load_matrix_sync(af[1][1], Ab + 16 * LDA + kof1, LDA);
                wmma::load_matrix_sync(bfr[1][0], Bb + kof1 * LDB, LDB);
                wmma::load_matrix_sync(bfr[1][1], Bb + kof1 * LDB + 16, LDB);
            }
#pragma unroll
            for (int q = 0; q < 2; q++)
#pragma unroll
                for (int r = 0; r < 2; r++)
                    wmma::mma_sync(acc[q][r], af[s][q], bfr[s][r], acc[q][r]);
        }
    }

    CP_WAIT0();          // drain trailing empty groups before overlaying stages with z
    __syncthreads();
    float* zs0 = (float*)smem;
    float* zs1 = (float*)(smem + Z1_OFF);
    float* zsw = w_k ? zs1 : zs0;
#pragma unroll
    for (int q = 0; q < 2; q++)
#pragma unroll
        for (int r = 0; r < 2; r++)
            wmma::store_matrix_sync(zsw + (w_m * 32 + 16 * q) * LDZ + (w_n * 32 + 16 * r),
                                    acc[q][r], LDZ, wmma::mem_row_major);
    __syncthreads();

    const int u  = tid & 15;
    const int bq = tid >> 4;
    const float bi = bsm[u], bf_ = bsm[16 + u], bg = bsm[32 + u], bo = bsm[48 + u];

#pragma unroll
    for (int j = 0; j < 4; j++) {
        const int m = bq * 4 + j;
        const size_t idx = (size_t)(bM + m) * UU + u0 + u;
        const float zi = zs0[m * LDZ + u]      + zs1[m * LDZ + u]      + bi;
        const float zf = zs0[m * LDZ + 16 + u] + zs1[m * LDZ + 16 + u] + bf_;
        const float zg = zs0[m * LDZ + 32 + u] + zs1[m * LDZ + 32 + u] + bg;
        const float zo = zs0[m * LDZ + 48 + u] + zs1[m * LDZ + 48 + u] + bo;
        const float ig = sigmoidf_(zi);
        const float fg = sigmoidf_(zf);
        const float gg = fmaxf(zg, 0.f);
        const float og = sigmoidf_(zo);
        const float c  = fg * cstate[idx] + ig * gg;
        cstate[idx] = c;
        hout[idx]   = __float2bfloat16_rn(og * fmaxf(c, 0.f));
    }
}

// Persistent: 128 CTAs, layer-2 weight tile resident in smem for the whole run.
__global__ void __launch_bounds__(NTHR, 1)
lstm_persistent(const float* __restrict__ b1, const float* __restrict__ b2)
{
    extern __shared__ __align__(1024) char smem[];
    uint32_t sb = (uint32_t)__cvta_generic_to_shared(smem);

    const int tid = threadIdx.x, wid = tid >> 5;
    const int bx = blockIdx.x;
    const int bM = (bx & 3) * 64;
    const int tile = bx >> 2;
    const int u0 = tile * 16;
    const int w_m = wid & 1, w_n = (wid >> 1) & 1, w_k = wid >> 2;

    float* bsm1 = (float*)(smem + BIAS_OFF);
    float* bsm2 = bsm1 + 64;
    if (tid < 64) {
        int g = tid >> 4, ui = tid & 15;
        bsm1[tid] = b1[g * UU + tile * 16 + ui];
        bsm2[tid] = b2[g * UU + tile * 16 + ui];
    }

    const bf16* img1b = g_img1 + (size_t)tile * (576 * NCOL);
    const bf16* img2b = g_img2 + (size_t)tile * (1024 * NCOL);

    // ---- prologue: load resident W2 tile (1024 x 64 -> [k][LDB=72]) ----
    {
        const char* src = (const char*)img2b;
        uint32_t dst = sb + WB2_OFF;
#pragma unroll 1
        for (int u = tid; u < 1024 * 8; u += NTHR) {
            int row = u >> 3, nq = u & 7;
            CP_ASYNC16(dst + (uint32_t)(row * (LDB * 2) + nq * 16), src + u * 16);
        }
        CP_COMMIT();
        CP_WAIT0();
    }
    __syncthreads();

    unsigned phase = 0;
#pragma unroll 1
    for (int t = 0; t < TT; t++) {
        gemm_phase<false>(g_xT + (size_t)t * BB * FF, FF, 1, g_h1[t & 1],
                          img1b, 9, bsm1, g_c1, g_h1[(t + 1) & 1],
                          smem, sb, tid, w_m, w_n, w_k, bM, u0);
        grid_barrier(++phase);
        gemm_phase<true>(g_h1[(t + 1) & 1], UU, 8, g_h2[t & 1],
                         (const bf16*)0, 16, bsm2, g_c2, g_h2[(t + 1) & 1],
                         smem, sb, tid, w_m, w_n, w_k, bM, u0);
        grid_barrier(++phase);
    }
}

__global__ void head_kernel(const float* __restrict__ Wd,
                            const float* __restrict__ bd,
                            float* __restrict__ out)
{
    const int b = threadIdx.x;
    float s = 0.f;
#pragma unroll 8
    for (int k = 0; k < UU; k++) s = fmaf(__bfloat162float(g_h2[0][b * UU + k]), Wd[k], s);
    out[b] = 1.f / (1.f + expf(-(s + bd[0])));
}

extern "C" void kernel_launch(void* const* d_in, const int* in_sizes, int n_in,
                              void* d_out, int out_size) {
    const float* x  = (const float*)d_in[0];
    const float* W1 = (const float*)d_in[1];
    const float* U1 = (const float*)d_in[2];
    const float* b1 = (const float*)d_in[3];
    const float* W2 = (const float*)d_in[4];
    const float* U2 = (const float*)d_in[5];
    const float* b2 = (const float*)d_in[6];
    const float* Wd = (const float*)d_in[7];
    const float* bd = (const float*)d_in[8];
    float* out = (float*)d_out;

    cudaFuncSetAttribute(lstm_persistent, cudaFuncAttributeMaxDynamicSharedMemorySize, SMEM_BYTES);

    prep_all_kernel<<<NB_ZERO + NB_X + NB_I1 + NB_I2, 256>>>(x, W1, U1, W2, U2);

    lstm_persistent<<<NCTA, NTHR, SMEM_BYTES>>>(b1, b2);

    head_kernel<<<1, 256>>>(Wd, bd, out);
}